// round 9
// baseline (speedup 1.0000x reference)
#include <cuda_runtime.h>
#include <cstdint>

#define IMG_H 1024
#define IMG_W 1024
#define IMG_C 3

// ---------------------------------------------------------------------------
// Compare-exchange + Lang's arbitrary-n bitonic networks (compile-time
// unrolled). The arbitrary-n merge BM is only valid for "valley" bitonic
// inputs (first floor(N/2) descending, last ceil(N/2) ascending) — exactly
// the shape BS feeds its own merge. All hand-built merge inputs follow it.
// ---------------------------------------------------------------------------
__device__ __forceinline__ void ce(float &a, float &b) {
    float lo = fminf(a, b);
    float hi = fmaxf(a, b);
    a = lo; b = hi;
}

__host__ __device__ constexpr int gplt(int n) {  // greatest power of two < n
    int k = 1;
    while (k < n) k <<= 1;
    return k >> 1;
}

template <int LO, int N, bool ASC>
struct BM {
    __device__ __forceinline__ static void run(float *a) {
        if constexpr (N > 1) {
            constexpr int M = gplt(N);
#pragma unroll
            for (int i = LO; i < LO + N - M; ++i) {
                if (ASC) ce(a[i], a[i + M]); else ce(a[i + M], a[i]);
            }
            BM<LO, M, ASC>::run(a);
            BM<LO + M, N - M, ASC>::run(a);
        }
    }
};

template <int LO, int N, bool ASC>
struct BS {
    __device__ __forceinline__ static void run(float *a) {
        if constexpr (N > 1) {
            constexpr int M = N / 2;
            BS<LO, M, !ASC>::run(a);           // first half opposite dir
            BS<LO + M, N - M, ASC>::run(a);    // second half same dir
            BM<LO, N, ASC>::run(a);            // valley merge
        }
    }
};

// ---------------------------------------------------------------------------
// Fused kernel.
//   Blocks [0, NB_BORDER)              : border pixels (generic 32-pad sort).
//   Blocks [NB_BORDER, NB_BORDER+NB_I) : interior pixels (pruned network).
// Border blocks get the LOWEST ids so the scheduler starts them first; their
// latency-bound sorts finish under the shadow of the interior wave.
// ---------------------------------------------------------------------------
#define PER_BORDER (5 * IMG_W + (IMG_H - 5) * 5)          // 10215 px/channel
#define NB_BORDER  ((IMG_C * PER_BORDER + 127) / 128)     // 240 blocks
#define NB_IX      4        // 4 x-blocks of 64 threads -> tx 0..255
#define NB_IY      510      // 510 y-blocks of 2 rows   -> y 2..1021 (use 2..1020)
#define NB_INTERIOR (NB_IX * NB_IY * IMG_C)               // 6120 blocks

__device__ __forceinline__ void do_interior(const float *__restrict__ img,
                                            float *__restrict__ out,
                                            int b) {
    const int tlocal = threadIdx.x;           // 0..127
    const int bx = b & 3;                     // b % 4
    const int by = (b >> 2) % NB_IY;
    const int ch = b / (NB_IX * NB_IY);

    const int tx = bx * 64 + (tlocal & 63);   // 0..255
    const int y  = 2 + by * 2 + (tlocal >> 6);
    if (tx > 254 || y > 1020) return;

    const int choff = ch * (IMG_H * IMG_W);
    const float *base = img + choff;
    const int x0 = 2 + 4 * tx;

    // Load 5 rows x 8 cols; col[c][r] = image[y-2+r][x0-2+c]
    float col[8][5];
    {
        int off = (y - 2) * IMG_W + (x0 - 2);   // 16B aligned (x0-2 = 4*tx)
#pragma unroll
        for (int r = 0; r < 5; ++r, off += IMG_W) {
            const float4 *p = reinterpret_cast<const float4 *>(base + off);
            float4 A = __ldg(p);
            float4 B = __ldg(p + 1);
            col[0][r] = A.x; col[1][r] = A.y; col[2][r] = A.z; col[3][r] = A.w;
            col[4][r] = B.x; col[5][r] = B.y; col[6][r] = B.z; col[7][r] = B.w;
        }
    }
#pragma unroll
    for (int c = 0; c < 8; ++c) BS<0, 5, true>::run(col[c]);

    // Valley merge of two sorted-ascending 5s -> sorted 10
    float P12[10], P34[10], P56[10];
    auto mk10 = [&](float *dst, const float *u, const float *v) {
#pragma unroll
        for (int i = 0; i < 5; ++i) { dst[i] = u[4 - i]; dst[5 + i] = v[i]; }
        BM<0, 10, true>::run(dst);     // valley: 5 desc + 5 asc
    };
    mk10(P12, col[1], col[2]);
    mk10(P34, col[3], col[4]);
    mk10(P56, col[5], col[6]);

    float S[20];
    auto mk20 = [&](const float *PL, const float *PR) {
#pragma unroll
        for (int i = 0; i < 10; ++i) { S[i] = PL[9 - i]; S[10 + i] = PR[i]; }
        BM<0, 20, true>::run(S);       // valley: 10 desc + 10 asc
        // only S[7..12] are consumed below; ptxas DCE prunes the rest
    };

    // median(25) = rank-5 (6th smallest) of sorted C(5) U sorted S[7..12].
    // Closed-form selection: answer = min( {max(C[i], B[4-i])}_{i=0..4},
    // B[5] ) with B[k] = S[7+k]. Exact: if the answer is C[i], pair (i,4-i)
    // produces it and all other candidates are >= it; symmetric for B.
    // 5 FMAX + 5 FMIN, fully parallel -> replaces the serial BM<11>.
    auto sel = [&](const float *cx) -> float {
        float c0 = fmaxf(cx[0], S[11]);
        float c1 = fmaxf(cx[1], S[10]);
        float c2 = fmaxf(cx[2], S[9]);
        float c3 = fmaxf(cx[3], S[8]);
        float c4 = fmaxf(cx[4], S[7]);
        float m01 = fminf(c0, c1);
        float m23 = fminf(c2, c3);
        float m45 = fminf(c4, S[12]);
        return fminf(fminf(m01, m23), m45);
    };

    // pixel 0 (x0)  : cols 0..4, shared 1..4 (P12,P34), extra col0
    // pixel 1 (x0+1): cols 1..5, shared 1..4,           extra col5
    // pixel 2 (x0+2): cols 2..6, shared 3..6 (P34,P56), extra col2
    // pixel 3 (x0+3): cols 3..7, shared 3..6,           extra col7
    mk20(P12, P34);
    float m0 = sel(col[0]);
    float m1 = sel(col[5]);
    mk20(P34, P56);
    float m2 = sel(col[2]);
    float m3 = sel(col[7]);

    float *orow = out + choff + y * IMG_W;
    orow[x0 + 0] = m0;
    orow[x0 + 1] = m1;
    orow[x0 + 2] = m2;
    if (x0 + 3 <= 1020) orow[x0 + 3] = m3;   // x=1021 handled by border path
}

__device__ __forceinline__ void do_border(const float *__restrict__ img,
                                          float *__restrict__ out,
                                          int b) {
    int tid = b * 128 + threadIdx.x;
    int ch = tid / PER_BORDER;
    if (ch >= IMG_C) return;
    int t = tid % PER_BORDER;

    int y, x;
    if (t < 5 * IMG_W) {                 // full rows {0,1,1021,1022,1023}
        int r = t >> 10;
        x = t & (IMG_W - 1);
        y = (r < 2) ? r : (IMG_H - 5 + r);
    } else {                              // rows 2..1020, cols {0,1,1021,1022,1023}
        int u = t - 5 * IMG_W;
        int r = u / 5, k = u % 5;
        y = 2 + r;
        x = (k < 2) ? k : (IMG_W - 5 + k);
    }

    const float *base = img + ch * (IMG_H * IMG_W);
    const float INF = __int_as_float(0x7f800000);

    float a[32];
    int idx = 0;
#pragma unroll
    for (int dy = -2; dy <= 2; ++dy) {
#pragma unroll
        for (int dx = -2; dx <= 2; ++dx) {
            int yy = y + dy, xx = x + dx;
            bool valid = (yy >= 0) && (yy <= IMG_H - 2) &&
                         (xx >= 0) && (xx <= IMG_W - 2);
            a[idx++] = valid ? base[yy * IMG_W + xx] : INF;
        }
    }
#pragma unroll
    for (int i = 25; i < 32; ++i) a[i] = INF;

    BS<0, 32, true>::run(a);

    int ny = min(y + 2, IMG_H - 2) - max(y - 2, 0) + 1;
    int nx = min(x + 2, IMG_W - 2) - max(x - 2, 0) + 1;
    int n = ny * nx;
    float lo = a[(n - 1) >> 1];
    float hi = a[n >> 1];
    out[ch * (IMG_H * IMG_W) + y * IMG_W + x] = 0.5f * (lo + hi);
}

__global__ void __launch_bounds__(128)
median_fused(const float *__restrict__ img, float *__restrict__ out) {
    int b = blockIdx.x;
    if (b < NB_BORDER) {
        do_border(img, out, b);               // scheduled first, hidden under
    } else {                                   // the interior wave
        do_interior(img, out, b - NB_BORDER);
    }
}

// ---------------------------------------------------------------------------
extern "C" void kernel_launch(void *const *d_in, const int *in_sizes, int n_in,
                              void *d_out, int out_size) {
    (void)in_sizes; (void)n_in; (void)out_size;
    const float *img = (const float *)d_in[0];
    float *out = (float *)d_out;

    median_fused<<<NB_BORDER + NB_INTERIOR, 128>>>(img, out);
}

// round 12
// speedup vs baseline: 1.0254x; 1.0254x over previous
#include <cuda_runtime.h>
#include <cstdint>

#define IMG_H 1024
#define IMG_W 1024
#define IMG_C 3

// ---------------------------------------------------------------------------
// Two compare-exchange flavors:
//   ce      : FMNMX pair (alu pipe).  Safe for +-inf.  2 instr.
//   ce_fma  : arithmetic CE on the fma pipe: 2 FADD + 1 FMUL + 2 FFMA-imm.
//             Exact to ~1 ulp; FINITE INPUTS ONLY (inf-inf = NaN).
// The interior column sorts use ce_fma to offload the saturated alu pipe
// (alu=68% of peak, fma=2%) — pipe-cycle balance: ~580 alu vs ~576 fma.
// ---------------------------------------------------------------------------
__device__ __forceinline__ void ce(float &a, float &b) {
    float lo = fminf(a, b);
    float hi = fmaxf(a, b);
    a = lo; b = hi;
}

__device__ __forceinline__ void ce_fma(float &a, float &b) {
    float s  = a + b;
    float d  = a - b;
    float ad = fabsf(d);            // folds into FFMA source modifier
    float hs = 0.5f * s;
    float mn = fmaf(ad, -0.5f, hs);
    float mx = fmaf(ad,  0.5f, hs);
    a = mn; b = mx;
}

__host__ __device__ constexpr int gplt(int n) {  // greatest power of two < n
    int k = 1;
    while (k < n) k <<= 1;
    return k >> 1;
}

// Bitonic merge, valley input required (first floor(N/2) desc, rest asc).
template <int LO, int N, bool ASC, bool FMA = false>
struct BM {
    __device__ __forceinline__ static void run(float *a) {
        if constexpr (N > 1) {
            constexpr int M = gplt(N);
#pragma unroll
            for (int i = LO; i < LO + N - M; ++i) {
                if (FMA) { if (ASC) ce_fma(a[i], a[i + M]); else ce_fma(a[i + M], a[i]); }
                else     { if (ASC) ce(a[i], a[i + M]);     else ce(a[i + M], a[i]); }
            }
            BM<LO, M, ASC, FMA>::run(a);
            BM<LO + M, N - M, ASC, FMA>::run(a);
        }
    }
};

// Lang's arbitrary-n bitonic sort.
template <int LO, int N, bool ASC, bool FMA = false>
struct BS {
    __device__ __forceinline__ static void run(float *a) {
        if constexpr (N > 1) {
            constexpr int M = N / 2;
            BS<LO, M, !ASC, FMA>::run(a);          // first half opposite dir
            BS<LO + M, N - M, ASC, FMA>::run(a);   // second half same dir
            BM<LO, N, ASC, FMA>::run(a);           // valley merge
        }
    }
};

// ---------------------------------------------------------------------------
// Fused kernel.
//   Blocks [0, NB_BORDER)              : border pixels (generic 32-pad sort).
//   Blocks [NB_BORDER, NB_BORDER+NB_I) : interior pixels (pruned network).
// Border blocks get the LOWEST ids so the scheduler starts them first; their
// latency-bound sorts finish under the shadow of the interior wave.
// ---------------------------------------------------------------------------
#define PER_BORDER (5 * IMG_W + (IMG_H - 5) * 5)          // 10215 px/channel
#define NB_BORDER  ((IMG_C * PER_BORDER + 127) / 128)     // 240 blocks
#define NB_IX      4        // 4 x-blocks of 64 threads -> tx 0..255
#define NB_IY      510      // 510 y-blocks of 2 rows   -> y 2..1021 (use 2..1020)
#define NB_INTERIOR (NB_IX * NB_IY * IMG_C)               // 6120 blocks

__device__ __forceinline__ void do_interior(const float *__restrict__ img,
                                            float *__restrict__ out,
                                            int b) {
    const int tlocal = threadIdx.x;           // 0..127
    const int bx = b & 3;                     // b % 4
    const int by = (b >> 2) % NB_IY;
    const int ch = b / (NB_IX * NB_IY);

    const int tx = bx * 64 + (tlocal & 63);   // 0..255
    const int y  = 2 + by * 2 + (tlocal >> 6);
    if (tx > 254 || y > 1020) return;

    const int choff = ch * (IMG_H * IMG_W);
    const float *base = img + choff;
    const int x0 = 2 + 4 * tx;

    // Load 5 rows x 8 cols; col[c][r] = image[y-2+r][x0-2+c]
    float col[8][5];
    {
        int off = (y - 2) * IMG_W + (x0 - 2);   // 16B aligned (x0-2 = 4*tx)
#pragma unroll
        for (int r = 0; r < 5; ++r, off += IMG_W) {
            const float4 *p = reinterpret_cast<const float4 *>(base + off);
            float4 A = __ldg(p);
            float4 B = __ldg(p + 1);
            col[0][r] = A.x; col[1][r] = A.y; col[2][r] = A.z; col[3][r] = A.w;
            col[4][r] = B.x; col[5][r] = B.y; col[6][r] = B.z; col[7][r] = B.w;
        }
    }
    // Column sorts on the fma pipe (finite data only; 8 independent chains)
#pragma unroll
    for (int c = 0; c < 8; ++c) BS<0, 5, true, true>::run(col[c]);

    // Valley merge of two sorted-ascending 5s -> sorted 10   (alu pipe)
    float P12[10], P34[10], P56[10];
    auto mk10 = [&](float *dst, const float *u, const float *v) {
#pragma unroll
        for (int i = 0; i < 5; ++i) { dst[i] = u[4 - i]; dst[5 + i] = v[i]; }
        BM<0, 10, true>::run(dst);     // valley: 5 desc + 5 asc
    };
    mk10(P12, col[1], col[2]);
    mk10(P34, col[3], col[4]);
    mk10(P56, col[5], col[6]);

    float S[20];
    auto mk20 = [&](const float *PL, const float *PR) {
#pragma unroll
        for (int i = 0; i < 10; ++i) { S[i] = PL[9 - i]; S[10 + i] = PR[i]; }
        BM<0, 20, true>::run(S);       // valley: 10 desc + 10 asc
        // only S[7..12] are consumed below; ptxas DCE prunes the rest
    };

    // median(25) = rank-5 (6th smallest) of sorted C(5) U sorted S[7..12].
    // Closed-form: min( {max(C[i], S[11-i])}_{i=0..4}, S[12] ). Exact.
    auto sel = [&](const float *cx) -> float {
        float c0 = fmaxf(cx[0], S[11]);
        float c1 = fmaxf(cx[1], S[10]);
        float c2 = fmaxf(cx[2], S[9]);
        float c3 = fmaxf(cx[3], S[8]);
        float c4 = fmaxf(cx[4], S[7]);
        float m01 = fminf(c0, c1);
        float m23 = fminf(c2, c3);
        float m45 = fminf(c4, S[12]);
        return fminf(fminf(m01, m23), m45);
    };

    // pixel 0 (x0)  : cols 0..4, shared 1..4 (P12,P34), extra col0
    // pixel 1 (x0+1): cols 1..5, shared 1..4,           extra col5
    // pixel 2 (x0+2): cols 2..6, shared 3..6 (P34,P56), extra col2
    // pixel 3 (x0+3): cols 3..7, shared 3..6,           extra col7
    mk20(P12, P34);
    float m0 = sel(col[0]);
    float m1 = sel(col[5]);
    mk20(P34, P56);
    float m2 = sel(col[2]);
    float m3 = sel(col[7]);

    float *orow = out + choff + y * IMG_W;
    orow[x0 + 0] = m0;
    orow[x0 + 1] = m1;
    orow[x0 + 2] = m2;
    if (x0 + 3 <= 1020) orow[x0 + 3] = m3;   // x=1021 handled by border path
}

__device__ __forceinline__ void do_border(const float *__restrict__ img,
                                          float *__restrict__ out,
                                          int b) {
    int tid = b * 128 + threadIdx.x;
    int ch = tid / PER_BORDER;
    if (ch >= IMG_C) return;
    int t = tid % PER_BORDER;

    int y, x;
    if (t < 5 * IMG_W) {                 // full rows {0,1,1021,1022,1023}
        int r = t >> 10;
        x = t & (IMG_W - 1);
        y = (r < 2) ? r : (IMG_H - 5 + r);
    } else {                              // rows 2..1020, cols {0,1,1021,1022,1023}
        int u = t - 5 * IMG_W;
        int r = u / 5, k = u % 5;
        y = 2 + r;
        x = (k < 2) ? k : (IMG_W - 5 + k);
    }

    const float *base = img + ch * (IMG_H * IMG_W);
    const float INF = __int_as_float(0x7f800000);

    float a[32];
    int idx = 0;
#pragma unroll
    for (int dy = -2; dy <= 2; ++dy) {
#pragma unroll
        for (int dx = -2; dx <= 2; ++dx) {
            int yy = y + dy, xx = x + dx;
            bool valid = (yy >= 0) && (yy <= IMG_H - 2) &&
                         (xx >= 0) && (xx <= IMG_W - 2);
            a[idx++] = valid ? base[yy * IMG_W + xx] : INF;
        }
    }
#pragma unroll
    for (int i = 25; i < 32; ++i) a[i] = INF;

    BS<0, 32, true>::run(a);   // FMNMX path: must stay inf-safe

    int ny = min(y + 2, IMG_H - 2) - max(y - 2, 0) + 1;
    int nx = min(x + 2, IMG_W - 2) - max(x - 2, 0) + 1;
    int n = ny * nx;
    float lo = a[(n - 1) >> 1];
    float hi = a[n >> 1];
    out[ch * (IMG_H * IMG_W) + y * IMG_W + x] = 0.5f * (lo + hi);
}

__global__ void __launch_bounds__(128, 9)
median_fused(const float *__restrict__ img, float *__restrict__ out) {
    int b = blockIdx.x;
    if (b < NB_BORDER) {
        do_border(img, out, b);               // scheduled first, hidden under
    } else {                                   // the interior wave
        do_interior(img, out, b - NB_BORDER);
    }
}

// ---------------------------------------------------------------------------
extern "C" void kernel_launch(void *const *d_in, const int *in_sizes, int n_in,
                              void *d_out, int out_size) {
    (void)in_sizes; (void)n_in; (void)out_size;
    const float *img = (const float *)d_in[0];
    float *out = (float *)d_out;

    median_fused<<<NB_BORDER + NB_INTERIOR, 128>>>(img, out);
}